// round 5
// baseline (speedup 1.0000x reference)
#include <cuda_runtime.h>
#include <math.h>

// Fixed problem shape (from setup_inputs)
#define Bb 2
#define L  2048
#define H  64
#define P  64
#define NS 128
#define CS 256
#define NC 8

// ---------------- scratch (static device globals; no runtime alloc) -------
__device__ float g_dt   [Bb*H*NC*CS];            // softplus(dt+bias)
__device__ float g_dacs [Bb*H*NC*CS];            // cumsum(dA) within chunk
__device__ float g_dAl  [Bb*H*NC];               // last cumsum per chunk
__device__ float g_states[(size_t)Bb*NC*H*P*NS]; // chunk end-state contribs
__device__ float g_prev  [(size_t)Bb*NC*H*P*NS]; // propagated prev states
__device__ float g_CB   [(size_t)Bb*NC*CS*CS];   // C @ B^T per (b,c)
__device__ float g_inter[(size_t)Bb*NC*H*CS*P];  // inter-chunk term [b,c,h,l,p]

// packed dual-FMA: {c.x,c.y} += {a.x,a.y}*{b.x,b.y}  (one FFMA2 instruction)
__device__ __forceinline__ float2 fma2(float2 a, float2 b, float2 c) {
    unsigned long long ua = *reinterpret_cast<unsigned long long*>(&a);
    unsigned long long ub = *reinterpret_cast<unsigned long long*>(&b);
    unsigned long long uc = *reinterpret_cast<unsigned long long*>(&c);
    asm("fma.rn.f32x2 %0, %1, %2, %0;" : "+l"(uc) : "l"(ua), "l"(ub));
    return *reinterpret_cast<float2*>(&uc);
}

// ---------------- K1: dt softplus + per-chunk cumsum ----------------------
__global__ void k_dt(const float* __restrict__ dt, const float* __restrict__ A,
                     const float* __restrict__ dtb) {
    int idx = blockIdx.x;               // b*H*NC
    int c = idx % NC;
    int h = (idx / NC) % H;
    int b = idx / (NC * H);
    int s = threadIdx.x;
    int lg = c * CS + s;

    float v = dt[((size_t)b * L + lg) * H + h] + dtb[h];
    float sp = (v > 20.f) ? v : log1pf(__expf(v));
    float dA = sp * A[h];

    __shared__ float sm[CS];
    sm[s] = dA;
    __syncthreads();
#pragma unroll
    for (int off = 1; off < CS; off <<= 1) {
        float pv = (s >= off) ? sm[s - off] : 0.f;
        __syncthreads();
        sm[s] += pv;
        __syncthreads();
    }
    int base = ((b * H + h) * NC + c) * CS;
    g_dt[base + s] = sp;
    g_dacs[base + s] = sm[s];
    if (s == CS - 1) g_dAl[(b * H + h) * NC + c] = sm[s];
}

// ---------------- K2: chunk_state, head-batched GEMM per (b,c) ------------
// out[(h,p), n] = sum_s (w[h,s]*x[s,h,p]) * B[s, n]   M=4096 N=128 K=256
// tile: 128 rows (2 heads) x 64 cols, k-tile 32
__global__ void __launch_bounds__(256, 2) k_state2(const float* __restrict__ x,
                                                   const float* __restrict__ Bm) {
    int blk = blockIdx.x;
    int nt = blk & 1; blk >>= 1;
    int mt = blk & 31; blk >>= 5;
    int bc = blk;                      // 0..15
    int b = bc >> 3, c = bc & 7;
    int h0 = mt * 2, m0 = mt * 128;

    __shared__ float As[128][34];      // x*w tile [m][k]
    __shared__ float Bs[64][34];       // B tile   [n][k]
    __shared__ float ws[2][CS];

    int t = threadIdx.x, ty = t >> 4, tx = t & 15;
#pragma unroll
    for (int hh = 0; hh < 2; hh++) {
        int dbase = ((b * H + h0 + hh) * NC + c) * CS;
        float dlast = g_dAl[(b * H + h0 + hh) * NC + c];
        ws[hh][t] = __expf(dlast - g_dacs[dbase + t]) * g_dt[dbase + t];
    }
    __syncthreads();

    float2 acc2[8][4];
#pragma unroll
    for (int i = 0; i < 8; i++)
#pragma unroll
        for (int j = 0; j < 4; j++) acc2[i][j] = make_float2(0.f, 0.f);

    for (int kt = 0; kt < CS; kt += 32) {
#pragma unroll
        for (int i = 0; i < 16; i++) {
            int e = t + 256 * i;
            int m = e & 127, k = e >> 7;
            size_t row = (size_t)(b * L + c * CS + kt + k);
            As[m][k] = x[row * 4096 + m0 + m] * ws[m >> 6][kt + k];
        }
#pragma unroll
        for (int i = 0; i < 8; i++) {
            int e = t + 256 * i;
            int n = e & 63, k = e >> 6;
            Bs[n][k] = Bm[(size_t)(b * L + c * CS + kt + k) * NS + nt * 64 + n];
        }
        __syncthreads();
#pragma unroll
        for (int k = 0; k < 32; k += 2) {
            float2 a2[8], b2[4];
#pragma unroll
            for (int i = 0; i < 8; i++) a2[i] = *(const float2*)&As[ty * 8 + i][k];
#pragma unroll
            for (int j = 0; j < 4; j++) b2[j] = *(const float2*)&Bs[tx + 16 * j][k];
#pragma unroll
            for (int i = 0; i < 8; i++)
#pragma unroll
                for (int j = 0; j < 4; j++) acc2[i][j] = fma2(a2[i], b2[j], acc2[i][j]);
        }
        __syncthreads();
    }
    size_t sbase = (size_t)bc * H * P * NS;
#pragma unroll
    for (int i = 0; i < 8; i++)
#pragma unroll
        for (int j = 0; j < 4; j++)
            g_states[sbase + (size_t)(m0 + ty * 8 + i) * NS + nt * 64 + tx + 16 * j] =
                acc2[i][j].x + acc2[i][j].y;
}

// ---------------- K3: state passing across chunks --------------------------
__global__ void k_pass(float* __restrict__ finals) {
    int e = blockIdx.x % 32;
    int h = (blockIdx.x / 32) % H;
    int b = blockIdx.x / (32 * H);
    int pn = e * 256 + threadIdx.x;    // 0..P*NS-1

    size_t cstride = (size_t)H * P * NS;
    size_t base = ((size_t)b * NC * H + h) * P * NS + pn;
    float run = 0.f;
#pragma unroll
    for (int c = 0; c < NC; c++) {
        size_t idx = base + (size_t)c * cstride;
        g_prev[idx] = run;
        run = run * __expf(g_dAl[(b * H + h) * NC + c]) + g_states[idx];
    }
    if (finals) finals[((size_t)(b * H + h)) * P * NS + pn] = run;
}

// ---------------- K4: CB[l,s] = sum_n C[l,n] B[s,n] (per b,c; tril tiles) --
__global__ void __launch_bounds__(256, 2) k_cb(const float* __restrict__ Cm,
                                               const float* __restrict__ Bm) {
    int bc = blockIdx.z;
    int b = bc / NC, c = bc % NC;
    if (blockIdx.x > blockIdx.y) return;  // upper-triangular tiles unused
    int l0 = blockIdx.y * 64, s0 = blockIdx.x * 64;

    __shared__ float Cs[64][34], Bs2[64][34];
    int t = threadIdx.x, ty = t >> 4, tx = t & 15;
    float2 acc2[4][4];
#pragma unroll
    for (int i = 0; i < 4; i++)
#pragma unroll
        for (int j = 0; j < 4; j++) acc2[i][j] = make_float2(0.f, 0.f);

    for (int nt = 0; nt < NS; nt += 32) {
#pragma unroll
        for (int i = 0; i < 8; i++) {
            int e = t + 256 * i;
            int r = e >> 5, k = e & 31;
            Cs[r][k]  = Cm[((size_t)b * L + c * CS + l0 + r) * NS + nt + k];
            Bs2[r][k] = Bm[((size_t)b * L + c * CS + s0 + r) * NS + nt + k];
        }
        __syncthreads();
#pragma unroll
        for (int k = 0; k < 32; k += 2) {
            float2 a2[4], b2[4];
#pragma unroll
            for (int i = 0; i < 4; i++) a2[i] = *(const float2*)&Cs[ty + 16 * i][k];
#pragma unroll
            for (int j = 0; j < 4; j++) b2[j] = *(const float2*)&Bs2[tx + 16 * j][k];
#pragma unroll
            for (int i = 0; i < 4; i++)
#pragma unroll
                for (int j = 0; j < 4; j++) acc2[i][j] = fma2(a2[i], b2[j], acc2[i][j]);
        }
        __syncthreads();
    }
    size_t cb = ((size_t)(b * NC + c)) * CS * CS;
#pragma unroll
    for (int i = 0; i < 4; i++)
#pragma unroll
        for (int j = 0; j < 4; j++)
            g_CB[cb + (size_t)(l0 + ty + 16 * i) * CS + s0 + tx + 16 * j] =
                acc2[i][j].x + acc2[i][j].y;
}

// ---------------- K4b: inter-chunk term, head-batched GEMM per (b,c) ------
// inter[l, (h,p)] = exp(dacs[h,l]) * sum_n C[l,n] prev[(h,p), n]
// M=256(l, 2 tiles of 128), N=4096((h,p), 64 tiles of 64 = 1 head each), K=128
__global__ void __launch_bounds__(256, 2) k_inter(const float* __restrict__ Cm) {
    int blk = blockIdx.x;
    int mt = blk & 63; blk >>= 6;      // head tile (= head index)
    int lt = blk & 1;  blk >>= 1;
    int bc = blk;                      // 0..15
    int b = bc >> 3, c = bc & 7;
    int h = mt;

    __shared__ float As[128][34];      // C tile [l][k]
    __shared__ float Ps[64][34];       // prev tile [p][k]
    __shared__ float sdl[128];

    int t = threadIdx.x, ty = t >> 4, tx = t & 15;
    int dbase = ((b * H + h) * NC + c) * CS + lt * 128;
    if (t < 128) sdl[t] = g_dacs[dbase + t];

    float2 acc2[8][4];
#pragma unroll
    for (int i = 0; i < 8; i++)
#pragma unroll
        for (int j = 0; j < 4; j++) acc2[i][j] = make_float2(0.f, 0.f);

    size_t pbase = (size_t)bc * H * P * NS + (size_t)(h * 64) * NS;
    for (int kt = 0; kt < NS; kt += 32) {
#pragma unroll
        for (int i = 0; i < 16; i++) {
            int e = t + 256 * i;
            int l = e >> 5, k = e & 31;
            As[l][k] = Cm[((size_t)b * L + c * CS + lt * 128 + l) * NS + kt + k];
        }
#pragma unroll
        for (int i = 0; i < 8; i++) {
            int e = t + 256 * i;
            int p = e >> 5, k = e & 31;
            Ps[p][k] = g_prev[pbase + (size_t)p * NS + kt + k];
        }
        __syncthreads();
#pragma unroll
        for (int k = 0; k < 32; k += 2) {
            float2 a2[8], b2[4];
#pragma unroll
            for (int i = 0; i < 8; i++) a2[i] = *(const float2*)&As[ty * 8 + i][k];
#pragma unroll
            for (int j = 0; j < 4; j++) b2[j] = *(const float2*)&Ps[tx + 16 * j][k];
#pragma unroll
            for (int i = 0; i < 8; i++)
#pragma unroll
                for (int j = 0; j < 4; j++) acc2[i][j] = fma2(a2[i], b2[j], acc2[i][j]);
        }
        __syncthreads();
    }
    size_t obase = ((size_t)(bc * H + h) * CS + lt * 128) * P;
#pragma unroll
    for (int i = 0; i < 8; i++) {
        float el = __expf(sdl[ty * 8 + i]);
#pragma unroll
        for (int j = 0; j < 4; j++)
            g_inter[obase + (size_t)(ty * 8 + i) * P + tx + 16 * j] =
                (acc2[i][j].x + acc2[i][j].y) * el;
    }
}

// ---------------- K5: chunk_scan intra + epilogue --------------------------
__global__ void __launch_bounds__(256, 2) k_scan(const float* __restrict__ x,
                                                 const float* __restrict__ z,
                                                 const float* __restrict__ D,
                                                 float* __restrict__ out) {
    int tmp = blockIdx.x;
    int lt = tmp & 1; tmp >>= 1;
    int h = tmp % H;  tmp /= H;
    int c = tmp % NC;
    int b = tmp / NC;
    int bc = b * NC + c;
    int l0 = lt * 128;

    __shared__ float As[128][34];   // score tile [r][k]
    __shared__ float Bs[64][34];    // x tile [p][k]
    __shared__ float sdall[CS], sdtall[CS];

    int t = threadIdx.x, ty = t >> 4, tx = t & 15;
    int dbase = ((b * H + h) * NC + c) * CS;
    sdall[t]  = g_dacs[dbase + t];
    sdtall[t] = g_dt[dbase + t];

    // init acc from inter-chunk term
    float2 acc2[8][4];
    size_t ibase = ((size_t)(bc * H + h) * CS + l0) * P;
#pragma unroll
    for (int i = 0; i < 8; i++)
#pragma unroll
        for (int j = 0; j < 4; j++) {
            acc2[i][j].x = g_inter[ibase + (size_t)(ty * 8 + i) * P + tx + 16 * j];
            acc2[i][j].y = 0.f;
        }
    __syncthreads();

    // intra-chunk masked scores  A'[l,s] = CB*exp(dacs[l]-dacs[s])*dt[s]
    size_t cbbase = ((size_t)bc) * CS * CS;
    int nkt = (lt == 0) ? 4 : 8;
    for (int kt = 0; kt < nkt; kt++) {
        int s0 = kt * 32;
#pragma unroll
        for (int i = 0; i < 16; i++) {
            int e = t + 256 * i;
            int r = e >> 5, k = e & 31;
            int l = l0 + r, s = s0 + k;
            float v = 0.f;
            if (s <= l)
                v = g_CB[cbbase + (size_t)l * CS + s] *
                    __expf(sdall[l0 + r] - sdall[s0 + k]) * sdtall[s0 + k];
            As[r][k] = v;
        }
#pragma unroll
        for (int i = 0; i < 8; i++) {
            int e = t + 256 * i;
            int sr = e >> 6, p = e & 63;
            Bs[p][sr] = x[(((size_t)b * L + c * CS + s0 + sr) * H + h) * P + p];
        }
        __syncthreads();
#pragma unroll
        for (int k = 0; k < 32; k += 2) {
            float2 a2[8], b2[4];
#pragma unroll
            for (int i = 0; i < 8; i++) a2[i] = *(const float2*)&As[ty * 8 + i][k];
#pragma unroll
            for (int j = 0; j < 4; j++) b2[j] = *(const float2*)&Bs[tx + 16 * j][k];
#pragma unroll
            for (int i = 0; i < 8; i++)
#pragma unroll
                for (int j = 0; j < 4; j++) acc2[i][j] = fma2(a2[i], b2[j], acc2[i][j]);
        }
        __syncthreads();
    }

    // Epilogue: fold k-parity, + x*D, * silu(z)
    float Dh = D[h];
#pragma unroll
    for (int i = 0; i < 8; i++) {
#pragma unroll
        for (int j = 0; j < 4; j++) {
            int l = l0 + ty * 8 + i, p = tx + 16 * j;
            size_t gi = (((size_t)b * L + c * CS + l) * H + h) * P + p;
            float xv = x[gi], zv = z[gi];
            float o = acc2[i][j].x + acc2[i][j].y + xv * Dh;
            float sil = zv / (1.f + __expf(-zv));
            out[gi] = o * sil;
        }
    }
}

// ---------------- launch ----------------------------------------------------
extern "C" void kernel_launch(void* const* d_in, const int* in_sizes, int n_in,
                              void* d_out, int out_size) {
    const float* x   = (const float*)d_in[0];
    const float* dt  = (const float*)d_in[1];
    const float* A   = (const float*)d_in[2];
    const float* Bm  = (const float*)d_in[3];
    const float* Cm  = (const float*)d_in[4];
    const float* D   = (const float*)d_in[5];
    const float* z   = (const float*)d_in[6];
    const float* dtb = (const float*)d_in[7];
    (void)in_sizes; (void)n_in;

    float* out = (float*)d_out;
    const int OUT_ELEMS = Bb * L * H * P;            // 16777216
    const int FIN_ELEMS = Bb * H * P * NS;           // 1048576
    float* finals = (out_size >= OUT_ELEMS + FIN_ELEMS) ? (out + OUT_ELEMS) : nullptr;

    k_dt    <<<Bb * H * NC, CS>>>(dt, A, dtb);
    k_state2<<<Bb * NC * 32 * 2, 256>>>(x, Bm);
    k_pass  <<<Bb * H * 32, 256>>>(finals);
    dim3 g4(4, 4, Bb * NC);
    k_cb    <<<g4, 256>>>(Cm, Bm);
    k_inter <<<Bb * NC * 2 * H, 256>>>(Cm);
    k_scan  <<<Bb * NC * H * 2, 256>>>(x, z, D, out);
}

// round 6
// speedup vs baseline: 1.0464x; 1.0464x over previous
#include <cuda_runtime.h>
#include <math.h>

// Fixed problem shape (from setup_inputs)
#define Bb 2
#define L  2048
#define H  64
#define P  64
#define NS 128
#define CS 256
#define NC 8

// ---------------- scratch (static device globals; no runtime alloc) -------
__device__ float g_dt   [Bb*H*NC*CS];            // softplus(dt+bias)
__device__ float g_dacs [Bb*H*NC*CS];            // cumsum(dA) within chunk
__device__ float g_dAl  [Bb*H*NC];               // last cumsum per chunk
__device__ float g_states[(size_t)Bb*NC*H*P*NS]; // chunk end-state contribs
__device__ float g_prev  [(size_t)Bb*NC*H*P*NS]; // propagated prev states
__device__ float g_CB   [(size_t)Bb*NC*CS*CS];   // C @ B^T per (b,c)
__device__ float g_xt   [(size_t)Bb*H*P*L];      // x transposed: [b,h,p,l]

// packed dual-FMA: {c.x,c.y} += {a.x,a.y}*{b.x,b.y}  (one FFMA2 instruction)
__device__ __forceinline__ float2 fma2(float2 a, float2 b, float2 c) {
    unsigned long long ua = *reinterpret_cast<unsigned long long*>(&a);
    unsigned long long ub = *reinterpret_cast<unsigned long long*>(&b);
    unsigned long long uc = *reinterpret_cast<unsigned long long*>(&c);
    asm("fma.rn.f32x2 %0, %1, %2, %0;" : "+l"(uc) : "l"(ua), "l"(ub));
    return *reinterpret_cast<float2*>(&uc);
}

// ---------------- K0: transpose x -> xt[b,h,p,l] ---------------------------
__global__ void k_xt(const float* __restrict__ x) {
    __shared__ float tile[32][33];
    int bc = blockIdx.z;
    int b = bc >> 3, c = bc & 7;
    int hp0 = blockIdx.x * 32, s0 = blockIdx.y * 32;
    int tx = threadIdx.x, ty = threadIdx.y;   // 32 x 8
#pragma unroll
    for (int j = 0; j < 4; j++)
        tile[ty + 8 * j][tx] = x[((size_t)(b * L + c * CS + s0 + ty + 8 * j)) * 4096 + hp0 + tx];
    __syncthreads();
#pragma unroll
    for (int j = 0; j < 4; j++)
        g_xt[((size_t)b * 4096 + hp0 + ty + 8 * j) * L + c * CS + s0 + tx] = tile[tx][ty + 8 * j];
}

// ---------------- K1: dt softplus + per-chunk cumsum ----------------------
__global__ void k_dt(const float* __restrict__ dt, const float* __restrict__ A,
                     const float* __restrict__ dtb) {
    int idx = blockIdx.x;               // b*H*NC
    int c = idx % NC;
    int h = (idx / NC) % H;
    int b = idx / (NC * H);
    int s = threadIdx.x;
    int lg = c * CS + s;

    float v = dt[((size_t)b * L + lg) * H + h] + dtb[h];
    float sp = (v > 20.f) ? v : log1pf(__expf(v));
    float dA = sp * A[h];

    __shared__ float sm[CS];
    sm[s] = dA;
    __syncthreads();
#pragma unroll
    for (int off = 1; off < CS; off <<= 1) {
        float pv = (s >= off) ? sm[s - off] : 0.f;
        __syncthreads();
        sm[s] += pv;
        __syncthreads();
    }
    int base = ((b * H + h) * NC + c) * CS;
    g_dt[base + s] = sp;
    g_dacs[base + s] = sm[s];
    if (s == CS - 1) g_dAl[(b * H + h) * NC + c] = sm[s];
}

// ---------------- K2: chunk_state, head-batched GEMM per (b,c) ------------
// out[(h,p), n] = sum_s (w[h,s]*x[s,h,p]) * B[s, n]   M=4096 N=128 K=256
// tile 128(m: 2 heads) x 64(n), k-tile 32, register-prefetch pipelined
__global__ void __launch_bounds__(256, 2) k_state2(const float* __restrict__ Bm) {
    int blk = blockIdx.x;
    int nt = blk & 1; blk >>= 1;
    int mt = blk & 31; blk >>= 5;
    int bc = blk;                      // 0..15
    int b = bc >> 3, c = bc & 7;
    int h0 = mt * 2, m0 = mt * 128;

    __shared__ float As[128][34];      // x*w tile [m][k]
    __shared__ float Bs[64][34];       // B tile   [n][k]
    __shared__ float ws[2][CS];

    int t = threadIdx.x, ty = t >> 4, tx = t & 15;
#pragma unroll
    for (int hh = 0; hh < 2; hh++) {
        int dbase = ((b * H + h0 + hh) * NC + c) * CS;
        float dlast = g_dAl[(b * H + h0 + hh) * NC + c];
        ws[hh][t] = __expf(dlast - g_dacs[dbase + t]) * g_dt[dbase + t];
    }

    // prefetch mapping:
    //  A: m = t>>1, k0 = (t&1)*16, 4 x float4 along k (from xt, s-contiguous)
    //  B: k = (t>>4) (+16*i), n4 = (t&15)*4, 2 x float4 along n
    int am = t >> 1, ak0 = (t & 1) * 16;
    int bk = t >> 4, bn4 = (t & 15) * 4;
    const float4* xa_p = (const float4*)(g_xt + ((size_t)b * 4096 + m0 + am) * L + c * CS + ak0);
    const float*  bm_p = Bm + (size_t)(b * L + c * CS) * NS + nt * 64 + bn4;

    float4 xa[4], bb[2];
#pragma unroll
    for (int i = 0; i < 4; i++) xa[i] = xa_p[i];
#pragma unroll
    for (int i = 0; i < 2; i++) bb[i] = *(const float4*)(bm_p + (size_t)(bk + 16 * i) * NS);

    float2 acc2[8][4];
#pragma unroll
    for (int i = 0; i < 8; i++)
#pragma unroll
        for (int j = 0; j < 4; j++) acc2[i][j] = make_float2(0.f, 0.f);

    int hw = am >> 6;   // which head for ws
    for (int kt = 0; kt < CS; kt += 32) {
        __syncthreads();
        // store prefetched regs to smem (apply decay weight to A)
#pragma unroll
        for (int i = 0; i < 4; i++) {
            int k = ak0 + 4 * i;
            float2 lo = make_float2(xa[i].x * ws[hw][kt + k],     xa[i].y * ws[hw][kt + k + 1]);
            float2 hi = make_float2(xa[i].z * ws[hw][kt + k + 2], xa[i].w * ws[hw][kt + k + 3]);
            *(float2*)&As[am][k]     = lo;
            *(float2*)&As[am][k + 2] = hi;
        }
#pragma unroll
        for (int i = 0; i < 2; i++) {
            Bs[bn4 + 0][bk + 16 * i] = bb[i].x;
            Bs[bn4 + 1][bk + 16 * i] = bb[i].y;
            Bs[bn4 + 2][bk + 16 * i] = bb[i].z;
            Bs[bn4 + 3][bk + 16 * i] = bb[i].w;
        }
        __syncthreads();
        // prefetch next k-tile
        if (kt + 32 < CS) {
            const float4* xp = (const float4*)(g_xt + ((size_t)b * 4096 + m0 + am) * L + c * CS + kt + 32 + ak0);
#pragma unroll
            for (int i = 0; i < 4; i++) xa[i] = xp[i];
#pragma unroll
            for (int i = 0; i < 2; i++)
                bb[i] = *(const float4*)(bm_p + (size_t)(kt + 32 + bk + 16 * i) * NS);
        }
#pragma unroll
        for (int k = 0; k < 32; k += 2) {
            float2 a2[8], b2[4];
#pragma unroll
            for (int i = 0; i < 8; i++) a2[i] = *(const float2*)&As[ty * 8 + i][k];
#pragma unroll
            for (int j = 0; j < 4; j++) b2[j] = *(const float2*)&Bs[tx + 16 * j][k];
#pragma unroll
            for (int i = 0; i < 8; i++)
#pragma unroll
                for (int j = 0; j < 4; j++) acc2[i][j] = fma2(a2[i], b2[j], acc2[i][j]);
        }
    }
    size_t sbase = (size_t)bc * H * P * NS;
#pragma unroll
    for (int i = 0; i < 8; i++)
#pragma unroll
        for (int j = 0; j < 4; j++)
            g_states[sbase + (size_t)(m0 + ty * 8 + i) * NS + nt * 64 + tx + 16 * j] =
                acc2[i][j].x + acc2[i][j].y;
}

// ---------------- K3: state passing across chunks --------------------------
__global__ void k_pass(float* __restrict__ finals) {
    int e = blockIdx.x % 32;
    int h = (blockIdx.x / 32) % H;
    int b = blockIdx.x / (32 * H);
    int pn = e * 256 + threadIdx.x;    // 0..P*NS-1

    size_t cstride = (size_t)H * P * NS;
    size_t base = ((size_t)b * NC * H + h) * P * NS + pn;
    float run = 0.f;
#pragma unroll
    for (int c = 0; c < NC; c++) {
        size_t idx = base + (size_t)c * cstride;
        g_prev[idx] = run;
        run = run * __expf(g_dAl[(b * H + h) * NC + c]) + g_states[idx];
    }
    if (finals) finals[((size_t)(b * H + h)) * P * NS + pn] = run;
}

// ---------------- K4: CB[l,s] = sum_n C[l,n] B[s,n] (per b,c; tril tiles) --
__global__ void __launch_bounds__(256, 2) k_cb(const float* __restrict__ Cm,
                                               const float* __restrict__ Bm) {
    int bc = blockIdx.z;
    int b = bc / NC, c = bc % NC;
    if (blockIdx.x > blockIdx.y) return;  // upper-triangular tiles unused
    int l0 = blockIdx.y * 64, s0 = blockIdx.x * 64;

    __shared__ float Cs[64][34], Bs2[64][34];
    int t = threadIdx.x, ty = t >> 4, tx = t & 15;
    float2 acc2[4][4];
#pragma unroll
    for (int i = 0; i < 4; i++)
#pragma unroll
        for (int j = 0; j < 4; j++) acc2[i][j] = make_float2(0.f, 0.f);

    for (int nt = 0; nt < NS; nt += 32) {
#pragma unroll
        for (int i = 0; i < 8; i++) {
            int e = t + 256 * i;
            int r = e >> 5, k = e & 31;
            Cs[r][k]  = Cm[((size_t)b * L + c * CS + l0 + r) * NS + nt + k];
            Bs2[r][k] = Bm[((size_t)b * L + c * CS + s0 + r) * NS + nt + k];
        }
        __syncthreads();
#pragma unroll
        for (int k = 0; k < 32; k += 2) {
            float2 a2[4], b2[4];
#pragma unroll
            for (int i = 0; i < 4; i++) a2[i] = *(const float2*)&Cs[ty + 16 * i][k];
#pragma unroll
            for (int j = 0; j < 4; j++) b2[j] = *(const float2*)&Bs2[tx + 16 * j][k];
#pragma unroll
            for (int i = 0; i < 4; i++)
#pragma unroll
                for (int j = 0; j < 4; j++) acc2[i][j] = fma2(a2[i], b2[j], acc2[i][j]);
        }
        __syncthreads();
    }
    size_t cb = ((size_t)(b * NC + c)) * CS * CS;
#pragma unroll
    for (int i = 0; i < 4; i++)
#pragma unroll
        for (int j = 0; j < 4; j++)
            g_CB[cb + (size_t)(l0 + ty + 16 * i) * CS + s0 + tx + 16 * j] =
                acc2[i][j].x + acc2[i][j].y;
}

// ---------------- K5: chunk_scan (inter + masked intra + epilogue) --------
// pipelined with register prefetch; x read from g_xt ([p][k] layout native)
__global__ void __launch_bounds__(256, 2) k_scan(const float* __restrict__ x,
                                                 const float* __restrict__ Cm,
                                                 const float* __restrict__ z,
                                                 const float* __restrict__ D,
                                                 float* __restrict__ out) {
    int tmp = blockIdx.x;
    int lt = tmp & 1; tmp >>= 1;
    int h = tmp % H;  tmp /= H;
    int c = tmp % NC;
    int b = tmp / NC;
    int bc = b * NC + c;
    int l0 = lt * 128;

    __shared__ float As[128][34];   // operand A tile [r][k]
    __shared__ float Bs[64][34];    // operand B tile [p][k]
    __shared__ float sdall[CS], sdtall[CS];

    int t = threadIdx.x, ty = t >> 4, tx = t & 15;
    int dbase = ((b * H + h) * NC + c) * CS;
    sdall[t]  = g_dacs[dbase + t];
    sdtall[t] = g_dt[dbase + t];

    float2 acc2[8][4];
#pragma unroll
    for (int i = 0; i < 8; i++)
#pragma unroll
        for (int j = 0; j < 4; j++) acc2[i][j] = make_float2(0.f, 0.f);

    // prefetch mappings (shared by both phases):
    //  A-tile: r = t>>1, k0 = (t&1)*16, 4 x float4
    //  B-tile: p = t>>2, k0 = (t&3)*8,  2 x float4
    int ar = t >> 1, ak0 = (t & 1) * 16;
    int bp = t >> 2, bk0 = (t & 3) * 8;

    // ---------- Phase A: inter-chunk term acc = C[l,:] . prev[p,:], K=128 --
    size_t pbase = (size_t)bc * H * P * NS + (size_t)(h * 64) * NS;
    const float* c_row = Cm + ((size_t)b * L + c * CS + l0 + ar) * NS;
    const float* p_row = g_prev + pbase + (size_t)bp * NS;

    float4 av[4], bv4[2];
#pragma unroll
    for (int i = 0; i < 4; i++) av[i] = *(const float4*)(c_row + ak0 + 4 * i);
#pragma unroll
    for (int i = 0; i < 2; i++) bv4[i] = *(const float4*)(p_row + bk0 + 4 * i);

    for (int nt = 0; nt < 4; nt++) {
        __syncthreads();
#pragma unroll
        for (int i = 0; i < 4; i++) {
            *(float2*)&As[ar][ak0 + 4 * i]     = make_float2(av[i].x, av[i].y);
            *(float2*)&As[ar][ak0 + 4 * i + 2] = make_float2(av[i].z, av[i].w);
        }
#pragma unroll
        for (int i = 0; i < 2; i++) {
            *(float2*)&Bs[bp][bk0 + 4 * i]     = make_float2(bv4[i].x, bv4[i].y);
            *(float2*)&Bs[bp][bk0 + 4 * i + 2] = make_float2(bv4[i].z, bv4[i].w);
        }
        __syncthreads();
        if (nt < 3) {
#pragma unroll
            for (int i = 0; i < 4; i++) av[i] = *(const float4*)(c_row + (nt + 1) * 32 + ak0 + 4 * i);
#pragma unroll
            for (int i = 0; i < 2; i++) bv4[i] = *(const float4*)(p_row + (nt + 1) * 32 + bk0 + 4 * i);
        }
#pragma unroll
        for (int k = 0; k < 32; k += 2) {
            float2 a2[8], b2[4];
#pragma unroll
            for (int i = 0; i < 8; i++) a2[i] = *(const float2*)&As[ty * 8 + i][k];
#pragma unroll
            for (int j = 0; j < 4; j++) b2[j] = *(const float2*)&Bs[tx + 16 * j][k];
#pragma unroll
            for (int i = 0; i < 8; i++)
#pragma unroll
                for (int j = 0; j < 4; j++) acc2[i][j] = fma2(a2[i], b2[j], acc2[i][j]);
        }
    }
    // scale inter term by exp(dA_cumsum[l])
#pragma unroll
    for (int i = 0; i < 8; i++) {
        float el = __expf(sdall[l0 + ty * 8 + i]);
#pragma unroll
        for (int j = 0; j < 4; j++) { acc2[i][j].x *= el; acc2[i][j].y *= el; }
    }

    // ---------- Phase B: intra-chunk masked scores @ x ---------------------
    size_t cbrow = ((size_t)bc) * CS * CS + (size_t)(l0 + ar) * CS;
    const float* xt_row = g_xt + ((size_t)b * 4096 + h * 64 + bp) * L + c * CS;
    float dlr = sdall[l0 + ar];

    int nkt = (lt == 0) ? 4 : 8;
    float4 cb4[4], xv4[2];
#pragma unroll
    for (int i = 0; i < 4; i++) cb4[i] = *(const float4*)(g_CB + cbrow + ak0 + 4 * i);
#pragma unroll
    for (int i = 0; i < 2; i++) xv4[i] = *(const float4*)(xt_row + bk0 + 4 * i);

    for (int kt = 0; kt < nkt; kt++) {
        int s0 = kt * 32;
        __syncthreads();
        // construct score tile from prefetched CB
#pragma unroll
        for (int i = 0; i < 4; i++) {
            int k = ak0 + 4 * i;
            float vq[4] = {cb4[i].x, cb4[i].y, cb4[i].z, cb4[i].w};
            float2 lo, hi;
#pragma unroll
            for (int q = 0; q < 4; q++) {
                int s = s0 + k + q;
                float v = 0.f;
                if (s <= l0 + ar)
                    v = vq[q] * __expf(dlr - sdall[s]) * sdtall[s];
                vq[q] = v;
            }
            lo = make_float2(vq[0], vq[1]);
            hi = make_float2(vq[2], vq[3]);
            *(float2*)&As[ar][k]     = lo;
            *(float2*)&As[ar][k + 2] = hi;
        }
#pragma unroll
        for (int i = 0; i < 2; i++) {
            *(float2*)&Bs[bp][bk0 + 4 * i]     = make_float2(xv4[i].x, xv4[i].y);
            *(float2*)&Bs[bp][bk0 + 4 * i + 2] = make_float2(xv4[i].z, xv4[i].w);
        }
        __syncthreads();
        if (kt + 1 < nkt) {
#pragma unroll
            for (int i = 0; i < 4; i++)
                cb4[i] = *(const float4*)(g_CB + cbrow + (s0 + 32) + ak0 + 4 * i);
#pragma unroll
            for (int i = 0; i < 2; i++)
                xv4[i] = *(const float4*)(xt_row + (s0 + 32) + bk0 + 4 * i);
        }
#pragma unroll
        for (int k = 0; k < 32; k += 2) {
            float2 a2[8], b2[4];
#pragma unroll
            for (int i = 0; i < 8; i++) a2[i] = *(const float2*)&As[ty * 8 + i][k];
#pragma unroll
            for (int j = 0; j < 4; j++) b2[j] = *(const float2*)&Bs[tx + 16 * j][k];
#pragma unroll
            for (int i = 0; i < 8; i++)
#pragma unroll
                for (int j = 0; j < 4; j++) acc2[i][j] = fma2(a2[i], b2[j], acc2[i][j]);
        }
    }

    // Epilogue: fold k-parity, + x*D, * silu(z)
    float Dh = D[h];
#pragma unroll
    for (int i = 0; i < 8; i++) {
#pragma unroll
        for (int j = 0; j < 4; j++) {
            int l = l0 + ty * 8 + i, p = tx + 16 * j;
            size_t gi = (((size_t)b * L + c * CS + l) * H + h) * P + p;
            float xv = x[gi], zv = z[gi];
            float o = acc2[i][j].x + acc2[i][j].y + xv * Dh;
            float sil = zv / (1.f + __expf(-zv));
            out[gi] = o * sil;
        }
    }
}

// ---------------- launch ----------------------------------------------------
extern "C" void kernel_launch(void* const* d_in, const int* in_sizes, int n_in,
                              void* d_out, int out_size) {
    const float* x   = (const float*)d_in[0];
    const float* dt  = (const float*)d_in[1];
    const float* A   = (const float*)d_in[2];
    const float* Bm  = (const float*)d_in[3];
    const float* Cm  = (const float*)d_in[4];
    const float* D   = (const float*)d_in[5];
    const float* z   = (const float*)d_in[6];
    const float* dtb = (const float*)d_in[7];
    (void)in_sizes; (void)n_in;

    float* out = (float*)d_out;
    const int OUT_ELEMS = Bb * L * H * P;            // 16777216
    const int FIN_ELEMS = Bb * H * P * NS;           // 1048576
    float* finals = (out_size >= OUT_ELEMS + FIN_ELEMS) ? (out + OUT_ELEMS) : nullptr;

    k_dt    <<<Bb * H * NC, CS>>>(dt, A, dtb);
    dim3 gx(128, 8, Bb * NC);
    k_xt    <<<gx, dim3(32, 8)>>>(x);
    k_state2<<<Bb * NC * 32 * 2, 256>>>(Bm);
    k_pass  <<<Bb * H * 32, 256>>>(finals);
    dim3 g4(4, 4, Bb * NC);
    k_cb    <<<g4, 256>>>(Cm, Bm);
    k_scan  <<<Bb * NC * H * 2, 256>>>(x, Cm, z, D, out);
}